// round 3
// baseline (speedup 1.0000x reference)
#include <cuda_runtime.h>
#include <cstdint>
#include <math.h>

#define N_STM 65536
#define N_LTM 65536
#define TOP_M 2048
#define NBIN  4096
#define TVOL  (5*96*96*96)

__device__ int                g_hist[NBIN];
__device__ int                g_scal[8];      // 0:T 1:count_above 2:sel_ctr 3:boundary_ctr
__device__ int                g_sel[TOP_M];
__device__ int                g_boundary[N_STM];
__device__ float              g_Kproj[TOP_M*64];
__device__ float              g_kp[TOP_M*64];
__device__ float              g_omega[TOP_M];
__device__ float              g_lkn[(size_t)N_LTM*64];
__device__ unsigned long long g_best[TOP_M];
__device__ unsigned long long g_key[TOP_M];
__device__ int                g_unm[TOP_M];
__device__ int                g_rank[TOP_M];
__device__ int                g_free[TOP_M];
__device__ float              g_tb0[TVOL];
__device__ float              g_tb1[TVOL];

__device__ __forceinline__ unsigned fmono(float f) {
    unsigned u = __float_as_uint(f);
    return (u & 0x80000000u) ? ~u : (u | 0x80000000u);
}
__device__ __forceinline__ float funmono(unsigned m) {
    unsigned u = (m & 0x80000000u) ? (m ^ 0x80000000u) : ~m;
    return __uint_as_float(u);
}
__device__ __forceinline__ unsigned long long dup2(float x) {
    unsigned long long r; unsigned xi = __float_as_uint(x);
    asm("mov.b64 %0, {%1,%2};" : "=l"(r) : "r"(xi), "r"(xi));
    return r;
}
__device__ __forceinline__ void fma2(unsigned long long& d,
                                     unsigned long long a, unsigned long long b) {
    asm("fma.rn.f32x2 %0, %1, %2, %0;" : "+l"(d) : "l"(a), "l"(b));
}
__device__ __forceinline__ unsigned long long stm_key(int i, float h) {
    return ((unsigned long long)__float_as_uint(h) << 32) | (0xFFFFFFFFu - (unsigned)i);
}

__global__ void k_init(const float* __restrict__ fat, float* __restrict__ oF) {
    int i = blockIdx.x * blockDim.x + threadIdx.x;
    if (i < NBIN) g_hist[i] = 0;
    if (i < 8)    g_scal[i] = 0;
    if (i < TOP_M) g_best[i] = 0ull;
    if (i == 0)   oF[0] = 0.2f * fat[0];
}

__global__ void k_stmv(const float* __restrict__ stm_V, float* __restrict__ oSV) {
    int w = threadIdx.x >> 5, lane = threadIdx.x & 31;
    size_t row = (size_t)blockIdx.x * 8 + w;
    float4 v = reinterpret_cast<const float4*>(stm_V)[row * 32 + lane];
    float sq = v.x*v.x + v.y*v.y + v.z*v.z + v.w*v.w;
    #pragma unroll
    for (int off = 16; off; off >>= 1) sq += __shfl_xor_sync(0xFFFFFFFFu, sq, off);
    float s = fminf(1.0f, 2.0f / (sqrtf(sq) + 1e-8f));
    reinterpret_cast<float4*>(oSV)[row * 32 + lane] =
        make_float4(v.x*s, v.y*s, v.z*s, v.w*s);
}

__global__ void k_hist(const float* __restrict__ h, const int* __restrict__ act) {
    int i = blockIdx.x * blockDim.x + threadIdx.x;
    if (i < N_STM && act[i] > 0) {
        int b = min(max((int)(h[i] * (float)NBIN), 0), NBIN - 1);
        atomicAdd(&g_hist[b], 1);
    }
}

__global__ void k_findT() {  // 1 block, 1024 threads
    __shared__ int s[1024];
    int t = threadIdx.x;
    int base = NBIN - 1 - 4 * t;  // chunk from top
    int h0 = g_hist[base], h1 = g_hist[base-1], h2 = g_hist[base-2], h3 = g_hist[base-3];
    int sum = h0 + h1 + h2 + h3;
    s[t] = sum;
    __syncthreads();
    for (int off = 1; off < 1024; off <<= 1) {
        int v = s[t], a = (t >= off) ? s[t - off] : 0;
        __syncthreads(); s[t] = v + a; __syncthreads();
    }
    int c = s[t] - sum;  // count strictly above this chunk
    int hh[4] = {h0, h1, h2, h3};
    #pragma unroll
    for (int q = 0; q < 4; ++q) {
        if (c < TOP_M && c + hh[q] >= TOP_M) { g_scal[0] = base - q; g_scal[1] = c; }
        c += hh[q];
    }
}

__global__ void k_compact(const float* __restrict__ h, const int* __restrict__ act) {
    int i = blockIdx.x * blockDim.x + threadIdx.x;
    if (i >= N_STM || act[i] <= 0) return;
    int T = g_scal[0];
    int b = min(max((int)(h[i] * (float)NBIN), 0), NBIN - 1);
    if (b > T)       g_sel[atomicAdd(&g_scal[2], 1)] = i;
    else if (b == T) g_boundary[atomicAdd(&g_scal[3], 1)] = i;
}

__global__ void k_boundary(const float* __restrict__ h) {
    int B = g_scal[3], need = TOP_M - g_scal[1];
    for (int c = threadIdx.x; c < B; c += blockDim.x) {
        int i = g_boundary[c];
        unsigned long long k = stm_key(i, h[i]);
        int r = 0;
        for (int t = 0; t < B; ++t) {
            int i2 = g_boundary[t];
            r += (stm_key(i2, h[i2]) > k);
        }
        if (r < need) g_sel[atomicAdd(&g_scal[2], 1)] = i;
    }
}

__global__ void k_lkn(const float* __restrict__ ltm_K, const int* __restrict__ act) {
    int j = blockIdx.x, c = threadIdx.x;
    float v = ltm_K[(size_t)j * 64 + c];
    float sq = v * v;
    #pragma unroll
    for (int off = 16; off; off >>= 1) sq += __shfl_xor_sync(0xFFFFFFFFu, sq, off);
    __shared__ float ws[2];
    if ((c & 31) == 0) ws[c >> 5] = sq;
    __syncthreads();
    float s = (act[j] > 0) ? (1.0f / (sqrtf(ws[0] + ws[1]) + 1e-8f)) : 0.0f;
    g_lkn[(size_t)j * 64 + c] = v * s;
}

__global__ void k_proj(const float* __restrict__ stm_K, const float* __restrict__ stm_h,
                       const float* __restrict__ W, const float* __restrict__ b) {
    int m = blockIdx.x, c = threadIdx.x;
    __shared__ float sK[16];
    int s = g_sel[m];
    if (c < 16) sK[c] = stm_K[(size_t)s * 16 + c];
    __syncthreads();
    float acc = b[c];
    #pragma unroll
    for (int k = 0; k < 16; ++k) acc = fmaf(sK[k], W[k * 64 + c], acc);
    float sq = acc * acc;
    #pragma unroll
    for (int off = 16; off; off >>= 1) sq += __shfl_xor_sync(0xFFFFFFFFu, sq, off);
    __shared__ float ws[2];
    if ((c & 31) == 0) ws[c >> 5] = sq;
    __syncthreads();
    g_Kproj[m * 64 + c] = acc;
    g_kp[m * 64 + c] = acc / (sqrtf(ws[0] + ws[1]) + 1e-8f);
    if (c == 0) g_omega[m] = 0.05f * stm_h[s];
}

// Fused sims GEMM + argmax. CTA tile 64m x 128j, K=64.
// kp_s [64k][64m]: LDS.64 -> packed f32x2 m-pair. lk_s [64k][128j]: conflict-free.
#define SIMS_SMEM ((64*64 + 64*128) * 4)  // 49152 B
__global__ void __launch_bounds__(256) k_sims() {
    extern __shared__ float sm[];
    float* kp_s = sm;           // [k][m]
    float* lk_s = sm + 4096;    // [k][j]
    const int tid = threadIdx.x;
    const int mb = tid >> 5;    // warp id 0..7 -> 8 m rows each
    const int jb = tid & 31;
    const int m0 = blockIdx.x * 64;

    for (int idx = tid; idx < 4096; idx += 256) {
        int m = idx >> 6, k = idx & 63;
        kp_s[k * 64 + m] = g_kp[(m0 + m) * 64 + k];
    }

    unsigned long long run[8];
    #pragma unroll
    for (int i = 0; i < 8; ++i) run[i] = 0ull;

    for (int s = blockIdx.y; s < 512; s += gridDim.y) {
        int j0 = s * 128;
        __syncthreads();
        #pragma unroll
        for (int it = 0; it < 8; ++it) {
            int idx = tid + it * 256;
            int r = idx >> 4, c4 = idx & 15;
            float4 v = reinterpret_cast<const float4*>(g_lkn)[(size_t)(j0 + r) * 16 + c4];
            lk_s[(c4 * 4 + 0) * 128 + r] = v.x;
            lk_s[(c4 * 4 + 1) * 128 + r] = v.y;
            lk_s[(c4 * 4 + 2) * 128 + r] = v.z;
            lk_s[(c4 * 4 + 3) * 128 + r] = v.w;
        }
        __syncthreads();

        unsigned long long acc[4][4];
        #pragma unroll
        for (int a = 0; a < 4; ++a)
            #pragma unroll
            for (int q = 0; q < 4; ++q) acc[a][q] = 0ull;

        #pragma unroll 4
        for (int k = 0; k < 64; ++k) {
            const unsigned long long* ap =
                reinterpret_cast<const unsigned long long*>(&kp_s[k * 64 + mb * 8]);
            unsigned long long a0 = ap[0], a1 = ap[1], a2 = ap[2], a3 = ap[3];
            #pragma unroll
            for (int q = 0; q < 4; ++q) {
                unsigned long long b2 = dup2(lk_s[k * 128 + jb + q * 32]);
                fma2(acc[0][q], a0, b2);
                fma2(acc[1][q], a1, b2);
                fma2(acc[2][q], a2, b2);
                fma2(acc[3][q], a3, b2);
            }
        }

        #pragma unroll
        for (int mp = 0; mp < 4; ++mp) {
            #pragma unroll
            for (int q = 0; q < 4; ++q) {
                unsigned lo = (unsigned)(acc[mp][q] & 0xFFFFFFFFull);
                unsigned hi = (unsigned)(acc[mp][q] >> 32);
                unsigned jinv = 0xFFFFFFFFu - (unsigned)(j0 + jb + q * 32);
                unsigned long long pl =
                    ((unsigned long long)fmono(__uint_as_float(lo)) << 32) | jinv;
                unsigned long long ph =
                    ((unsigned long long)fmono(__uint_as_float(hi)) << 32) | jinv;
                if (pl > run[2 * mp])     run[2 * mp]     = pl;
                if (ph > run[2 * mp + 1]) run[2 * mp + 1] = ph;
            }
        }
    }

    #pragma unroll
    for (int i = 0; i < 8; ++i) {
        #pragma unroll
        for (int off = 16; off; off >>= 1) {
            unsigned long long o = __shfl_xor_sync(0xFFFFFFFFu, run[i], off);
            if (o > run[i]) run[i] = o;
        }
        if (jb == 0) atomicMax(&g_best[m0 + mb * 8 + i], run[i]);
    }
}

__global__ void k_matched(const float* __restrict__ stm_V, const float* __restrict__ stm_e,
                          const float* __restrict__ stm_h,
                          float* __restrict__ oK, float* __restrict__ oV,
                          float* __restrict__ oe, float* __restrict__ oh) {
    int m = blockIdx.x, c = threadIdx.x;
    unsigned long long p = g_best[m];
    float sim = funmono((unsigned)(p >> 32));
    int j = (int)(0xFFFFFFFFu - (unsigned)(p & 0xFFFFFFFFull));
    bool matched = (sim >= 0.5f);
    int s = g_sel[m];
    float om = g_omega[m];
    if (c == 0) {
        g_unm[m] = matched ? 0 : 1;
        g_key[m] = stm_key(s, stm_h[s]);
        if (matched) atomicAdd(&oh[j], om);
    }
    if (matched) {
        atomicAdd(&oK[(size_t)j * 64 + c], om * g_Kproj[m * 64 + c]);
        atomicAdd(&oV[(size_t)j * 128 + c], om * stm_V[(size_t)s * 128 + c]);
        atomicAdd(&oV[(size_t)j * 128 + 64 + c], om * stm_V[(size_t)s * 128 + 64 + c]);
        if (c < 4) atomicAdd(&oe[(size_t)j * 4 + c], om * stm_e[(size_t)s * 4 + c]);
    }
}

__global__ void k_rank() {  // 8 blocks x 256
    __shared__ unsigned long long sk[TOP_M];
    __shared__ unsigned char su[TOP_M];
    int t = threadIdx.x;
    for (int i = t; i < TOP_M; i += 256) { sk[i] = g_key[i]; su[i] = (unsigned char)g_unm[i]; }
    __syncthreads();
    int m = blockIdx.x * 256 + t;
    if (g_unm[m]) {
        unsigned long long k = sk[m];
        int r = 0;
        for (int i = 0; i < TOP_M; ++i) r += (su[i] && sk[i] > k);
        g_rank[m] = r;
    }
}

__global__ void k_freeslots(const int* __restrict__ act) {  // 1 block x 1024
    __shared__ int sc[1024];
    int t = threadIdx.x, base = t * 64, cnt = 0;
    #pragma unroll 8
    for (int i = 0; i < 64; ++i) cnt += (act[base + i] == 0);
    sc[t] = cnt;
    __syncthreads();
    for (int off = 1; off < 1024; off <<= 1) {
        int v = sc[t], a = (t >= off) ? sc[t - off] : 0;
        __syncthreads(); sc[t] = v + a; __syncthreads();
    }
    int p = sc[t] - cnt;
    for (int i = 0; i < 64; ++i)
        if (act[base + i] == 0) { if (p < TOP_M) g_free[p] = base + i; ++p; }
}

__global__ void k_unmatch(const float* __restrict__ stm_V, const float* __restrict__ stm_e,
                          float* __restrict__ oK, float* __restrict__ oV,
                          float* __restrict__ oe, float* __restrict__ oh) {
    int m = blockIdx.x;
    if (!g_unm[m]) return;
    int slot = g_free[g_rank[m]], c = threadIdx.x, s = g_sel[m];
    oK[(size_t)slot * 64 + c] = g_Kproj[m * 64 + c];
    oV[(size_t)slot * 128 + c] = stm_V[(size_t)s * 128 + c];
    oV[(size_t)slot * 128 + 64 + c] = stm_V[(size_t)s * 128 + 64 + c];
    if (c < 4) oe[(size_t)slot * 4 + c] = stm_e[(size_t)s * 4 + c];
    if (c == 0) oh[slot] = g_omega[m];
}

__device__ __forceinline__ void gw(float* w, float& inv) {
    w[0] = 1.0f; float sum = 1.0f;
    #pragma unroll
    for (int i = 1; i < 7; ++i) {
        w[i] = expf(-0.5f * (float)(i * i) / 4.0f);
        sum += 2.0f * w[i];
    }
    inv = 1.0f / sum;
}
__global__ void k_blur(const float* __restrict__ in, float* __restrict__ outp, int stride) {
    float w[7], inv; gw(w, inv);
    int idx = blockIdx.x * blockDim.x + threadIdx.x;
    if (idx >= TVOL) return;
    int x = (idx / stride) % 96;
    float acc = in[idx] * w[0];
    #pragma unroll
    for (int t = 1; t < 7; ++t) {
        float a = (x - t >= 0) ? in[idx - t * stride] : 0.0f;
        float b = (x + t < 96) ? in[idx + t * stride] : 0.0f;
        acc += (a + b) * w[t];
    }
    outp[idx] = acc * inv;
}
__global__ void k_blur_merge(const float* __restrict__ in, const float* __restrict__ ltm_t,
                             float* __restrict__ oT) {
    float w[7], inv; gw(w, inv);
    int idx = blockIdx.x * blockDim.x + threadIdx.x;
    if (idx >= TVOL) return;
    int x = idx % 96;
    float acc = in[idx] * w[0];
    #pragma unroll
    for (int t = 1; t < 7; ++t) {
        float a = (x - t >= 0) ? in[idx - t] : 0.0f;
        float b = (x + t < 96) ? in[idx + t] : 0.0f;
        acc += (a + b) * w[t];
    }
    float xi = (idx < 96 * 96 * 96) ? 0.005f : 0.003f;
    oT[idx] = ltm_t[idx] + xi * (acc * inv);
}

extern "C" void kernel_launch(void* const* d_in, const int* in_sizes, int n_in,
                              void* d_out, int out_size) {
    (void)in_sizes; (void)n_in; (void)out_size;
    const float* stm_K   = (const float*)d_in[0];
    const float* stm_V   = (const float*)d_in[1];
    const float* stm_e   = (const float*)d_in[2];
    const float* stm_h   = (const float*)d_in[3];
    const float* ltm_K   = (const float*)d_in[4];
    const float* ltm_V   = (const float*)d_in[5];
    const float* ltm_e   = (const float*)d_in[6];
    const float* ltm_h   = (const float*)d_in[7];
    const float* W       = (const float*)d_in[8];
    const float* b       = (const float*)d_in[9];
    const float* stm_t   = (const float*)d_in[10];
    const float* ltm_t   = (const float*)d_in[11];
    const float* fatigue = (const float*)d_in[12];
    const int*   stm_act = (const int*)d_in[13];
    const int*   ltm_act = (const int*)d_in[14];

    float* out = (float*)d_out;
    float* oK  = out;                 // 65536*64
    float* oV  = out + 4194304;       // 65536*128
    float* oe  = out + 12582912;      // 65536*4
    float* oh  = out + 12845056;      // 65536
    float* oSV = out + 12910592;      // 65536*128
    float* oT  = out + 21299200;      // 5*96^3
    float* oF  = out + 25722880;      // 1

    cudaMemcpyAsync(oK, ltm_K, (size_t)4194304 * 4, cudaMemcpyDeviceToDevice, 0);
    cudaMemcpyAsync(oV, ltm_V, (size_t)8388608 * 4, cudaMemcpyDeviceToDevice, 0);
    cudaMemcpyAsync(oe, ltm_e, (size_t)262144 * 4, cudaMemcpyDeviceToDevice, 0);
    cudaMemcpyAsync(oh, ltm_h, (size_t)65536 * 4, cudaMemcpyDeviceToDevice, 0);

    k_init<<<16, 256>>>(fatigue, oF);
    k_stmv<<<8192, 256>>>(stm_V, oSV);
    k_hist<<<256, 256>>>(stm_h, stm_act);
    k_findT<<<1, 1024>>>();
    k_compact<<<256, 256>>>(stm_h, stm_act);
    k_boundary<<<1, 256>>>(stm_h);
    k_lkn<<<65536, 64>>>(ltm_K, ltm_act);
    k_proj<<<2048, 64>>>(stm_K, stm_h, W, b);
    k_sims<<<dim3(32, 9), 256, SIMS_SMEM>>>();
    k_matched<<<2048, 64>>>(stm_V, stm_e, stm_h, oK, oV, oe, oh);
    k_rank<<<8, 256>>>();
    k_freeslots<<<1, 1024>>>(ltm_act);
    k_unmatch<<<2048, 64>>>(stm_V, stm_e, oK, oV, oe, oh);

    int tb = (TVOL + 255) / 256;
    k_blur<<<tb, 256>>>(stm_t, g_tb0, 96 * 96);   // axis D
    k_blur<<<tb, 256>>>(g_tb0, g_tb1, 96);        // axis H
    k_blur_merge<<<tb, 256>>>(g_tb1, ltm_t, oT);  // axis W + merge
}

// round 4
// speedup vs baseline: 1.3223x; 1.3223x over previous
#include <cuda_runtime.h>
#include <cstdint>
#include <math.h>

#define N_STM 65536
#define N_LTM 65536
#define TOP_M 2048
#define NBIN  4096
#define TVOL  (5*96*96*96)

// scratch (static init = 0; every kernel restores its state for graph replay)
__device__ int                g_hist[NBIN];
__device__ int                g_scal[8];   // 0:T 1:cnt_above 2:sel_ctr 3:bnd_ctr 4:n_act 5:n_stages
__device__ int                g_sel[TOP_M];
__device__ int                g_boundary[N_STM];
__device__ float              g_Kproj[TOP_M*64];
__device__ float              g_kpT[64*TOP_M];            // [k][m]
__device__ float              g_omega[TOP_M];
__device__ float              g_lknC[(size_t)(N_LTM+128)*64];  // compacted active lkn
__device__ unsigned           g_ajinv[N_LTM+128];         // ~orig_j per compacted row
__device__ unsigned long long g_best[TOP_M];
__device__ unsigned long long g_key[TOP_M];
__device__ int                g_unm[TOP_M];
__device__ int                g_rank[TOP_M];
__device__ int                g_free[TOP_M];
__device__ float              g_tb0[TVOL];
__device__ float              g_tb1[TVOL];

__device__ __forceinline__ unsigned fmono(float f) {
    unsigned u = __float_as_uint(f);
    return (u & 0x80000000u) ? ~u : (u | 0x80000000u);
}
__device__ __forceinline__ float funmono(unsigned m) {
    unsigned u = (m & 0x80000000u) ? (m ^ 0x80000000u) : ~m;
    return __uint_as_float(u);
}
__device__ __forceinline__ unsigned long long dup2(float x) {
    unsigned long long r; unsigned xi = __float_as_uint(x);
    asm("mov.b64 %0, {%1,%2};" : "=l"(r) : "r"(xi), "r"(xi));
    return r;
}
__device__ __forceinline__ void fma2(unsigned long long& d,
                                     unsigned long long a, unsigned long long b) {
    asm("fma.rn.f32x2 %0, %1, %2, %0;" : "+l"(d) : "l"(a), "l"(b));
}
__device__ __forceinline__ unsigned long long stm_key(int i, float h) {
    return ((unsigned long long)__float_as_uint(h) << 32) | (0xFFFFFFFFu - (unsigned)i);
}
__device__ __forceinline__ int hbin(float h) {
    return min(max((int)(h * (float)NBIN), 0), NBIN - 1);
}

// ---- 1: ltm_K normalize + active compaction  |  stm histogram ------------
__global__ void k_histlkn(const float* __restrict__ ltm_K, const int* __restrict__ ltm_act,
                          const float* __restrict__ stm_h, const int* __restrict__ stm_act) {
    __shared__ float part[8];
    __shared__ int sact[4];
    __shared__ int sbase;
    int tid = threadIdx.x;
    int g = tid >> 6, c = tid & 63, wid = tid >> 5, lane = tid & 31;
    int j = blockIdx.x * 4 + g;
    float v = ltm_K[(size_t)j * 64 + c];
    float sq = v * v;
    #pragma unroll
    for (int off = 16; off; off >>= 1) sq += __shfl_xor_sync(0xFFFFFFFFu, sq, off);
    if (lane == 0) part[wid] = sq;
    int a = (ltm_act[j] > 0) ? 1 : 0;
    if (c == 0) sact[g] = a;
    __syncthreads();
    if (tid == 0) {
        int tot = sact[0] + sact[1] + sact[2] + sact[3];
        sbase = tot ? atomicAdd(&g_scal[4], tot) : 0;
    }
    __syncthreads();
    if (a) {
        int off = 0;
        #pragma unroll
        for (int x = 0; x < 4; ++x) if (x < g) off += sact[x];
        int pos = sbase + off;
        float tot = part[g * 2] + part[g * 2 + 1];
        g_lknC[(size_t)pos * 64 + c] = v / (sqrtf(tot) + 1e-8f);
        if (c == 0) g_ajinv[pos] = 0xFFFFFFFFu - (unsigned)j;
    }
    int i = blockIdx.x * 256 + tid;
    if (i < N_STM && stm_act[i] > 0) atomicAdd(&g_hist[hbin(stm_h[i])], 1);
}

// ---- 2: threshold bin + pad compacted tail + misc init --------------------
__global__ void k_findT(const float* __restrict__ fat, float* __restrict__ oF) {
    __shared__ int s[1024];
    int t = threadIdx.x;
    int base = NBIN - 1 - 4 * t;
    int h0 = g_hist[base], h1 = g_hist[base-1], h2 = g_hist[base-2], h3 = g_hist[base-3];
    g_hist[base] = 0; g_hist[base-1] = 0; g_hist[base-2] = 0; g_hist[base-3] = 0;
    int sum = h0 + h1 + h2 + h3;
    s[t] = sum;
    __syncthreads();
    for (int off = 1; off < 1024; off <<= 1) {
        int v = s[t], a2 = (t >= off) ? s[t - off] : 0;
        __syncthreads(); s[t] = v + a2; __syncthreads();
    }
    int c = s[t] - sum;
    int hh[4] = {h0, h1, h2, h3};
    #pragma unroll
    for (int q = 0; q < 4; ++q) {
        if (c < TOP_M && c + hh[q] >= TOP_M) { g_scal[0] = base - q; g_scal[1] = c; }
        c += hh[q];
    }
    int n_act = g_scal[4];
    // zero-pad 128 rows after compacted region
    for (int idx = t; idx < 128 * 64; idx += 1024)
        g_lknC[(size_t)(n_act + (idx >> 6)) * 64 + (idx & 63)] = 0.0f;
    if (t < 128) g_ajinv[n_act + t] = 0u;
    if (t == 0) {
        g_scal[5] = (n_act + 127) >> 7;
        g_scal[2] = 0; g_scal[3] = 0; g_scal[4] = 0;
        oF[0] = 0.2f * fat[0];
    }
}

// ---- 3: top-M compaction + boundary tie-break (one block) ------------------
__global__ void k_compactB(const float* __restrict__ h, const int* __restrict__ act) {
    int t = threadIdx.x;
    int T = g_scal[0];
    for (int i = t; i < N_STM; i += 1024) {
        if (act[i] > 0) {
            int b = hbin(h[i]);
            if (b > T)       g_sel[atomicAdd(&g_scal[2], 1)] = i;
            else if (b == T) g_boundary[atomicAdd(&g_scal[3], 1)] = i;
        }
    }
    __syncthreads();
    int B = g_scal[3], need = TOP_M - g_scal[1];
    for (int c = t; c < B; c += 1024) {
        int i = g_boundary[c];
        unsigned long long k = stm_key(i, h[i]);
        int r = 0;
        for (int q = 0; q < B; ++q) {
            int i2 = g_boundary[q];
            r += (stm_key(i2, h[i2]) > k);
        }
        if (r < need) g_sel[atomicAdd(&g_scal[2], 1)] = i;
    }
}

// ---- 4: projection + kp normalize (writes transposed kpT) ------------------
__global__ void k_proj(const float* __restrict__ stm_K, const float* __restrict__ stm_h,
                       const float* __restrict__ W, const float* __restrict__ b) {
    int m = blockIdx.x, c = threadIdx.x;
    __shared__ float sK[16];
    __shared__ float ws[2];
    int s = g_sel[m];
    if (c < 16) sK[c] = stm_K[(size_t)s * 16 + c];
    __syncthreads();
    float acc = b[c];
    #pragma unroll
    for (int k = 0; k < 16; ++k) acc = fmaf(sK[k], W[k * 64 + c], acc);
    float sq = acc * acc;
    #pragma unroll
    for (int off = 16; off; off >>= 1) sq += __shfl_xor_sync(0xFFFFFFFFu, sq, off);
    if ((c & 31) == 0) ws[c >> 5] = sq;
    __syncthreads();
    g_Kproj[m * 64 + c] = acc;
    g_kpT[c * TOP_M + m] = acc / (sqrtf(ws[0] + ws[1]) + 1e-8f);
    if (c == 0) g_omega[m] = 0.05f * stm_h[s];
}

// ---- 5: stm_V norm clip -----------------------------------------------------
__global__ void k_stmv(const float* __restrict__ stm_V, float* __restrict__ oSV) {
    int w = threadIdx.x >> 5, lane = threadIdx.x & 31;
    size_t row = (size_t)blockIdx.x * 8 + w;
    float4 v = reinterpret_cast<const float4*>(stm_V)[row * 32 + lane];
    float sq = v.x*v.x + v.y*v.y + v.z*v.z + v.w*v.w;
    #pragma unroll
    for (int off = 16; off; off >>= 1) sq += __shfl_xor_sync(0xFFFFFFFFu, sq, off);
    float s = fminf(1.0f, 2.0f / (sqrtf(sq) + 1e-8f));
    reinterpret_cast<float4*>(oSV)[row * 32 + lane] =
        make_float4(v.x*s, v.y*s, v.z*s, v.w*s);
}

// ---- 6: fused sims GEMM + argmax over compacted active set ----------------
// CTA 64m x 128j, thread tile 8m(4x f32x2) x 4j. kp_s[k][64m] (conflict-free
// both ways), lk_s[j][65] (b-load stride 65 conflict-free).
#define SIMS_SMEM ((64*64 + 128*65 + 128) * 4)  // 50176 B
__global__ void __launch_bounds__(256, 2) k_sims() {
    extern __shared__ float sm[];
    float* kp_s = sm;                      // [k][64]
    float* lk_s = sm + 64 * 64;            // [j][65]
    unsigned* jinv_s = (unsigned*)(sm + 64 * 64 + 128 * 65);
    const int tid = threadIdx.x;
    const int mb = tid >> 5;   // warp id -> 8 m rows
    const int jb = tid & 31;
    const int m0 = blockIdx.x * 64;
    const int ns = g_scal[5];

    for (int idx = tid; idx < 4096; idx += 256) {
        int m = idx & 63, k = idx >> 6;            // lanes: consecutive m
        kp_s[k * 64 + m] = g_kpT[k * TOP_M + m0 + m];
    }

    unsigned long long run[8];
    #pragma unroll
    for (int i = 0; i < 8; ++i) run[i] = 0ull;

    for (int s = blockIdx.y; s < ns; s += gridDim.y) {
        int j0 = s * 128;
        __syncthreads();
        #pragma unroll
        for (int it = 0; it < 8; ++it) {
            int idx = tid + it * 256;
            int r = idx >> 4, c4 = idx & 15;
            float4 v = reinterpret_cast<const float4*>(g_lknC)[(size_t)(j0 + r) * 16 + c4];
            float* dst = &lk_s[r * 65 + c4 * 4];
            dst[0] = v.x; dst[1] = v.y; dst[2] = v.z; dst[3] = v.w;
        }
        if (tid < 128) jinv_s[tid] = g_ajinv[j0 + tid];
        __syncthreads();

        unsigned long long acc[4][4];
        #pragma unroll
        for (int a = 0; a < 4; ++a)
            #pragma unroll
            for (int q = 0; q < 4; ++q) acc[a][q] = 0ull;

        #pragma unroll 4
        for (int k = 0; k < 64; ++k) {
            const unsigned long long* ap =
                reinterpret_cast<const unsigned long long*>(&kp_s[k * 64 + mb * 8]);
            unsigned long long a0 = ap[0], a1 = ap[1], a2 = ap[2], a3 = ap[3];
            #pragma unroll
            for (int q = 0; q < 4; ++q) {
                unsigned long long b2 = dup2(lk_s[(jb + q * 32) * 65 + k]);
                fma2(acc[0][q], a0, b2);
                fma2(acc[1][q], a1, b2);
                fma2(acc[2][q], a2, b2);
                fma2(acc[3][q], a3, b2);
            }
        }

        #pragma unroll
        for (int mp = 0; mp < 4; ++mp) {
            #pragma unroll
            for (int q = 0; q < 4; ++q) {
                unsigned lo = (unsigned)(acc[mp][q] & 0xFFFFFFFFull);
                unsigned hi = (unsigned)(acc[mp][q] >> 32);
                unsigned jinv = jinv_s[jb + q * 32];
                unsigned long long pl =
                    ((unsigned long long)fmono(__uint_as_float(lo)) << 32) | jinv;
                unsigned long long ph =
                    ((unsigned long long)fmono(__uint_as_float(hi)) << 32) | jinv;
                if (pl > run[2 * mp])     run[2 * mp]     = pl;
                if (ph > run[2 * mp + 1]) run[2 * mp + 1] = ph;
            }
        }
    }

    #pragma unroll
    for (int i = 0; i < 8; ++i) {
        #pragma unroll
        for (int off = 16; off; off >>= 1) {
            unsigned long long o = __shfl_xor_sync(0xFFFFFFFFu, run[i], off);
            if (o > run[i]) run[i] = o;
        }
        if (jb == 0) atomicMax(&g_best[m0 + mb * 8 + i], run[i]);
    }
}

// ---- 7: matched scatter-add (+ restore g_best for replay) -----------------
__global__ void k_matched(const float* __restrict__ stm_V, const float* __restrict__ stm_e,
                          const float* __restrict__ stm_h,
                          float* __restrict__ oK, float* __restrict__ oV,
                          float* __restrict__ oe, float* __restrict__ oh) {
    int m = blockIdx.x, c = threadIdx.x;
    __shared__ unsigned long long sp;
    if (c == 0) { sp = g_best[m]; g_best[m] = 0ull; }
    __syncthreads();
    unsigned long long p = sp;
    float sim = funmono((unsigned)(p >> 32));
    int j = (int)(0xFFFFFFFFu - (unsigned)(p & 0xFFFFFFFFull));
    bool matched = (sim >= 0.5f);
    int s = g_sel[m];
    float om = g_omega[m];
    if (c == 0) {
        g_unm[m] = matched ? 0 : 1;
        g_key[m] = stm_key(s, stm_h[s]);
        if (matched) atomicAdd(&oh[j], om);
    }
    if (matched) {
        atomicAdd(&oK[(size_t)j * 64 + c], om * g_Kproj[m * 64 + c]);
        atomicAdd(&oV[(size_t)j * 128 + c], om * stm_V[(size_t)s * 128 + c]);
        atomicAdd(&oV[(size_t)j * 128 + 64 + c], om * stm_V[(size_t)s * 128 + 64 + c]);
        if (c < 4) atomicAdd(&oe[(size_t)j * 4 + c], om * stm_e[(size_t)s * 4 + c]);
    }
}

// ---- 8: rank unmatched (h desc, idx asc — matches jax stable order) --------
__global__ void k_rank() {
    __shared__ unsigned long long sk[TOP_M];
    __shared__ unsigned char su[TOP_M];
    int t = threadIdx.x;
    for (int i = t; i < TOP_M; i += 256) { sk[i] = g_key[i]; su[i] = (unsigned char)g_unm[i]; }
    __syncthreads();
    int m = blockIdx.x * 256 + t;
    if (g_unm[m]) {
        unsigned long long k = sk[m];
        int r = 0;
        for (int i = 0; i < TOP_M; ++i) r += (su[i] && sk[i] > k);
        g_rank[m] = r;
    }
}

// ---- 9: first TOP_M inactive slots (ascending) -----------------------------
__global__ void k_freeslots(const int* __restrict__ act) {
    __shared__ int sc[1024];
    int t = threadIdx.x, base = t * 64, cnt = 0;
    #pragma unroll 8
    for (int i = 0; i < 64; ++i) cnt += (act[base + i] == 0);
    sc[t] = cnt;
    __syncthreads();
    for (int off = 1; off < 1024; off <<= 1) {
        int v = sc[t], a = (t >= off) ? sc[t - off] : 0;
        __syncthreads(); sc[t] = v + a; __syncthreads();
    }
    int p = sc[t] - cnt;
    for (int i = 0; i < 64; ++i)
        if (act[base + i] == 0) { if (p < TOP_M) g_free[p] = base + i; ++p; }
}

// ---- 10: unmatched fresh-slot writes ---------------------------------------
__global__ void k_unmatch(const float* __restrict__ stm_V, const float* __restrict__ stm_e,
                          float* __restrict__ oK, float* __restrict__ oV,
                          float* __restrict__ oe, float* __restrict__ oh) {
    int m = blockIdx.x;
    if (!g_unm[m]) return;
    int slot = g_free[g_rank[m]], c = threadIdx.x, s = g_sel[m];
    oK[(size_t)slot * 64 + c] = g_Kproj[m * 64 + c];
    oV[(size_t)slot * 128 + c] = stm_V[(size_t)s * 128 + c];
    oV[(size_t)slot * 128 + 64 + c] = stm_V[(size_t)s * 128 + 64 + c];
    if (c < 4) oe[(size_t)slot * 4 + c] = stm_e[(size_t)s * 4 + c];
    if (c == 0) oh[slot] = g_omega[m];
}

// ---- gaussian blur ----------------------------------------------------------
__device__ __forceinline__ void gw(float* w, float& inv) {
    w[0] = 1.0f; float sum = 1.0f;
    #pragma unroll
    for (int i = 1; i < 7; ++i) {
        w[i] = expf(-0.5f * (float)(i * i) / 4.0f);
        sum += 2.0f * w[i];
    }
    inv = 1.0f / sum;
}
__global__ void k_blur(const float* __restrict__ in, float* __restrict__ outp, int stride) {
    float w[7], inv; gw(w, inv);
    int idx = blockIdx.x * blockDim.x + threadIdx.x;
    if (idx >= TVOL) return;
    int x = (idx / stride) % 96;
    float acc = in[idx] * w[0];
    #pragma unroll
    for (int t = 1; t < 7; ++t) {
        float a = (x - t >= 0) ? in[idx - t * stride] : 0.0f;
        float b = (x + t < 96) ? in[idx + t * stride] : 0.0f;
        acc += (a + b) * w[t];
    }
    outp[idx] = acc * inv;
}
__global__ void k_blur_merge(const float* __restrict__ in, const float* __restrict__ ltm_t,
                             float* __restrict__ oT) {
    float w[7], inv; gw(w, inv);
    int idx = blockIdx.x * blockDim.x + threadIdx.x;
    if (idx >= TVOL) return;
    int x = idx % 96;
    float acc = in[idx] * w[0];
    #pragma unroll
    for (int t = 1; t < 7; ++t) {
        float a = (x - t >= 0) ? in[idx - t] : 0.0f;
        float b = (x + t < 96) ? in[idx + t] : 0.0f;
        acc += (a + b) * w[t];
    }
    float xi = (idx < 96 * 96 * 96) ? 0.005f : 0.003f;
    oT[idx] = ltm_t[idx] + xi * (acc * inv);
}

extern "C" void kernel_launch(void* const* d_in, const int* in_sizes, int n_in,
                              void* d_out, int out_size) {
    (void)in_sizes; (void)n_in; (void)out_size;
    const float* stm_K   = (const float*)d_in[0];
    const float* stm_V   = (const float*)d_in[1];
    const float* stm_e   = (const float*)d_in[2];
    const float* stm_h   = (const float*)d_in[3];
    const float* ltm_K   = (const float*)d_in[4];
    const float* ltm_V   = (const float*)d_in[5];
    const float* ltm_e   = (const float*)d_in[6];
    const float* ltm_h   = (const float*)d_in[7];
    const float* W       = (const float*)d_in[8];
    const float* b       = (const float*)d_in[9];
    const float* stm_t   = (const float*)d_in[10];
    const float* ltm_t   = (const float*)d_in[11];
    const float* fatigue = (const float*)d_in[12];
    const int*   stm_act = (const int*)d_in[13];
    const int*   ltm_act = (const int*)d_in[14];

    float* out = (float*)d_out;
    float* oK  = out;                 // 65536*64
    float* oV  = out + 4194304;       // 65536*128
    float* oe  = out + 12582912;      // 65536*4
    float* oh  = out + 12845056;      // 65536
    float* oSV = out + 12910592;      // 65536*128
    float* oT  = out + 21299200;      // 5*96^3
    float* oF  = out + 25722880;      // 1

    static bool attr_set = false;
    if (!attr_set) {
        cudaFuncSetAttribute(k_sims, cudaFuncAttributeMaxDynamicSharedMemorySize, SIMS_SMEM);
        attr_set = true;
    }

    k_histlkn<<<16384, 256>>>(ltm_K, ltm_act, stm_h, stm_act);
    k_findT<<<1, 1024>>>(fatigue, oF);
    k_compactB<<<1, 1024>>>(stm_h, stm_act);
    k_proj<<<2048, 64>>>(stm_K, stm_h, W, b);
    k_stmv<<<8192, 256>>>(stm_V, oSV);
    k_sims<<<dim3(32, 9), 256, SIMS_SMEM>>>();

    cudaMemcpyAsync(oK, ltm_K, (size_t)4194304 * 4, cudaMemcpyDeviceToDevice, 0);
    cudaMemcpyAsync(oV, ltm_V, (size_t)8388608 * 4, cudaMemcpyDeviceToDevice, 0);
    cudaMemcpyAsync(oe, ltm_e, (size_t)262144 * 4, cudaMemcpyDeviceToDevice, 0);
    cudaMemcpyAsync(oh, ltm_h, (size_t)65536 * 4, cudaMemcpyDeviceToDevice, 0);

    k_matched<<<2048, 64>>>(stm_V, stm_e, stm_h, oK, oV, oe, oh);
    k_rank<<<8, 256>>>();
    k_freeslots<<<1, 1024>>>(ltm_act);
    k_unmatch<<<2048, 64>>>(stm_V, stm_e, oK, oV, oe, oh);

    int tb = (TVOL + 255) / 256;
    k_blur<<<tb, 256>>>(stm_t, g_tb0, 96 * 96);   // axis D
    k_blur<<<tb, 256>>>(g_tb0, g_tb1, 96);        // axis H
    k_blur_merge<<<tb, 256>>>(g_tb1, ltm_t, oT);  // axis W + merge
}